// round 10
// baseline (speedup 1.0000x reference)
#include <cuda_runtime.h>
#include <cuda_fp16.h>
#include <cstdint>

#define NTOK 8192
#define HCH  2048
#define DH   128

// ---------------- device scratch ----------------
__device__ __align__(16) __half g_xh[NTOK * HCH];
__device__ __align__(16) __half g_wh[384 * HCH];
__device__ __align__(16) __half g_qh[NTOK * DH];   // scale folded
__device__ __align__(16) __half g_kh[NTOK * DH];
__device__ __align__(16) __half g_vh[NTOK * DH];
__device__ __align__(16) float  g_O[2][NTOK * DH]; // unnormalized per split
__device__ float g_l[2][NTOK];
__device__ uint8_t g_mask8[(size_t)NTOK * NTOK];
__device__ const uint8_t* g_mptr;

// ---------------- helpers ----------------
__device__ __forceinline__ uint32_t smem_u32(const void* p) {
  uint32_t a;
  asm("{ .reg .u64 t; cvta.to.shared.u64 t, %1; cvt.u32.u64 %0, t; }" : "=r"(a) : "l"(p));
  return a;
}
__device__ __forceinline__ void ldm_x4(uint32_t* r, uint32_t a) {
  asm volatile("ldmatrix.sync.aligned.m8n8.x4.shared.b16 {%0,%1,%2,%3}, [%4];"
    : "=r"(r[0]), "=r"(r[1]), "=r"(r[2]), "=r"(r[3]) : "r"(a));
}
__device__ __forceinline__ void ldm_x4t(uint32_t* r, uint32_t a) {
  asm volatile("ldmatrix.sync.aligned.m8n8.x4.trans.shared.b16 {%0,%1,%2,%3}, [%4];"
    : "=r"(r[0]), "=r"(r[1]), "=r"(r[2]), "=r"(r[3]) : "r"(a));
}
__device__ __forceinline__ void stm_x4(uint32_t a, uint32_t r0, uint32_t r1,
                                       uint32_t r2, uint32_t r3) {
  asm volatile("stmatrix.sync.aligned.m8n8.x4.shared.b16 [%0], {%1,%2,%3,%4};"
    :: "r"(a), "r"(r0), "r"(r1), "r"(r2), "r"(r3) : "memory");
}
__device__ __forceinline__ void mma16816(float* d, const uint32_t* a, const uint32_t* b) {
  asm volatile("mma.sync.aligned.m16n8k16.row.col.f32.f16.f16.f32 "
    "{%0,%1,%2,%3}, {%4,%5,%6,%7}, {%8,%9}, {%0,%1,%2,%3};"
    : "+f"(d[0]), "+f"(d[1]), "+f"(d[2]), "+f"(d[3])
    : "r"(a[0]), "r"(a[1]), "r"(a[2]), "r"(a[3]), "r"(b[0]), "r"(b[1]));
}
__device__ __forceinline__ void cp16(uint32_t dst, const void* src) {
  asm volatile("cp.async.cg.shared.global [%0], [%1], 16;" :: "r"(dst), "l"(src) : "memory");
}
__device__ __forceinline__ void cp8(uint32_t dst, const void* src) {
  asm volatile("cp.async.ca.shared.global [%0], [%1], 8;" :: "r"(dst), "l"(src) : "memory");
}
#define CP_COMMIT() asm volatile("cp.async.commit_group;" ::: "memory")
#define CP_WAIT0()  asm volatile("cp.async.wait_group 0;" ::: "memory")
__device__ __forceinline__ __half2 hexp2_(__half2 x) {
  uint32_t r, a = *(uint32_t*)&x;
  asm("ex2.approx.f16x2 %0, %1;" : "=r"(r) : "r"(a));
  return *(__half2*)&r;
}
__device__ __forceinline__ uint32_t pack_h2(float x, float y) {
  __half2 h = __floats2half2_rn(x, y);
  return *(uint32_t*)&h;
}

// ---------------- mask detect + compact (fused) ----------------
__global__ __launch_bounds__(256) void mask_cvt_kernel(const unsigned* __restrict__ m,
                                                       const uint8_t* __restrict__ morig) {
  __shared__ int s_ok;
  if (threadIdx.x == 0) {
    int ok = 1;
    for (int i = 0; i < 64; i++) {
      unsigned w = m[i];
      if (w > 1u && w != 0x3f800000u) { ok = 0; break; }
    }
    s_ok = ok;
    if (blockIdx.x == 0) g_mptr = ok ? (const uint8_t*)g_mask8 : morig;
  }
  __syncthreads();
  if (!s_ok) return;
  size_t i = (size_t)blockIdx.x * 256 + threadIdx.x;   // 16 outputs each
  const uint4* src = (const uint4*)m + i * 4;
  uint4 a = src[0], b = src[1], c = src[2], d = src[3];
  uint4 o;
  o.x = (a.x?1u:0u)|((a.y?1u:0u)<<8)|((a.z?1u:0u)<<16)|((a.w?1u:0u)<<24);
  o.y = (b.x?1u:0u)|((b.y?1u:0u)<<8)|((b.z?1u:0u)<<16)|((b.w?1u:0u)<<24);
  o.z = (c.x?1u:0u)|((c.y?1u:0u)<<8)|((c.z?1u:0u)<<16)|((c.w?1u:0u)<<24);
  o.w = (d.x?1u:0u)|((d.y?1u:0u)<<8)|((d.z?1u:0u)<<16)|((d.w?1u:0u)<<24);
  *(uint4*)(g_mask8 + i * 16) = o;
}

// ---------------- fp32 -> fp16 (x and W fused) ----------------
#define NX4 (NTOK * HCH / 4)
#define NW4 (384 * HCH / 4)
__global__ __launch_bounds__(256) void cvt_kernel(const float* __restrict__ x,
                                                  const float* __restrict__ w) {
  int i = blockIdx.x * 256 + threadIdx.x;
  const float* src;
  __half* dst;
  int j;
  if (i < NX4) { src = x; dst = g_xh; j = i; }
  else         { src = w; dst = g_wh; j = i - NX4; }
  float4 v = ((const float4*)src)[j];
  uint2 o; o.x = pack_h2(v.x, v.y); o.y = pack_h2(v.z, v.w);
  ((uint2*)dst)[j] = o;
}

// ---------------- QKV GEMM (mma.sync fp16, cp.async double-buffered) ----------------
__global__ __launch_bounds__(256, 2) void qkv_kernel() {
  extern __shared__ __align__(16) char smem[];
  const uint32_t sb = smem_u32(smem);
  const int tid = threadIdx.x, lane = tid & 31, wid = tid >> 5;
  const int wr = wid & 3, wc = wid >> 2;
  const int g = lane >> 2, c4 = lane & 3;
  const int m0 = blockIdx.x * 64;
  const int which = blockIdx.y;
  const __half* wsrc = g_wh + (size_t)which * 128 * HCH;

  float acc[8][4];
#pragma unroll
  for (int nt = 0; nt < 8; nt++)
#pragma unroll
    for (int r = 0; r < 4; r++) acc[nt][r] = 0.f;

  const int x7 = lane & 7, hiA = lane >> 4, hiB = (lane >> 3) & 1, q2 = (lane >> 4) & 1;
  const int l15 = lane & 15;

  auto issue = [&](int kc) {
    uint32_t bufA = sb + (uint32_t)(kc & 1) * 8192;
    uint32_t bufB = sb + 16384 + (uint32_t)(kc & 1) * 16384;
#pragma unroll
    for (int i = 0; i < 2; i++) {
      int idx = tid + i * 256;
      int r = idx >> 3, ch = idx & 7;
      uint32_t sw = (uint32_t)r * 128 + (uint32_t)((ch ^ (r & 7)) << 4);
      cp16(bufA + sw, g_xh + (size_t)(m0 + r) * HCH + kc * 64 + ch * 8);
    }
#pragma unroll
    for (int i = 0; i < 4; i++) {
      int idx = tid + i * 256;
      int r = idx >> 3, ch = idx & 7;
      uint32_t sw = (uint32_t)r * 128 + (uint32_t)((ch ^ (r & 7)) << 4);
      cp16(bufB + sw, wsrc + (size_t)r * HCH + kc * 64 + ch * 8);
    }
    CP_COMMIT();
  };

  issue(0);
  for (int kc = 0; kc < 32; kc++) {
    CP_WAIT0();
    __syncthreads();
    if (kc < 31) issue(kc + 1);
    const uint32_t bufA = sb + (uint32_t)(kc & 1) * 8192;
    const uint32_t bufB = sb + 16384 + (uint32_t)(kc & 1) * 16384;
    const uint32_t aBase = bufA + (uint32_t)(wr * 16 + l15) * 128;
    const uint32_t bBase = bufB + (uint32_t)(wc * 64 + x7) * 128;
#pragma unroll
    for (int ks = 0; ks < 4; ks++) {
      uint32_t a0[4];
      ldm_x4(a0, aBase + (((ks * 2 + hiA) ^ x7) << 4));
#pragma unroll
      for (int nt = 0; nt < 8; nt += 2) {
        uint32_t b[4];
        ldm_x4(b, bBase + (uint32_t)(nt + q2) * 8 * 128 + (((ks * 2 + hiB) ^ x7) << 4));
        mma16816(acc[nt], a0, b);
        mma16816(acc[nt + 1], a0, b + 2);
      }
    }
  }

  const float sc = (which == 0) ? (1.4426950408889634f / 128.0f) : 1.0f;
  __half* dst = (which == 0) ? g_qh : (which == 1) ? g_kh : g_vh;
#pragma unroll
  for (int h = 0; h < 2; h++) {
    int row = m0 + wr * 16 + g + h * 8;
#pragma unroll
    for (int nt = 0; nt < 8; nt++) {
      int col = wc * 64 + nt * 8 + c4 * 2;
      *(uint32_t*)(dst + (size_t)row * DH + col) =
          pack_h2(acc[nt][h * 2] * sc, acc[nt][h * 2 + 1] * sc);
    }
  }
}

// ---------------- attention (512 threads, 16 warps 4x4) ----------------
// grid 128 = 64 q-tiles x 2 kv-splits. BM=BN=128. Each warp: 32x32 tile.
// smem: K 2x32KB, V 2x32KB, Q 32KB, P 32KB, mask 2x17KB (stride 136) = 226KB
#define SK 0
#define SV 65536
#define SQ 131072
#define SP 163840
#define SM2 196608
#define MSTRIDE 136
#define MBUF (128 * MSTRIDE)
#define A_SMEM (SM2 + 2 * MBUF)

__global__ __launch_bounds__(512, 1) void attn_kernel() {
  extern __shared__ __align__(16) char smem[];
  const uint32_t sb = smem_u32(smem);
  const int tid = threadIdx.x, lane = tid & 31, wid = tid >> 5;
  const int wr = wid & 3, wc = wid >> 2;      // 4 row-groups x 4 col-groups
  const int g = lane >> 2, c4 = lane & 3;
  const int qt = blockIdx.x >> 1;
  const int qbase = qt * 128;
  const int split = blockIdx.x & 1;
  const uint8_t* mp = g_mptr;
  const int barid = wr + 1;

  const int x7 = lane & 7, hiA = lane >> 4, hiB = (lane >> 3) & 1, q2 = (lane >> 4) & 1;
  const int l15 = lane & 15;
  const int t8 = lane >> 3, hh = t8 & 1, ntp = t8 >> 1, r8 = lane & 7;

  auto issue = [&](int kb) {
    const int kcol = split * 4096 + kb * 128;
    const uint32_t kB = sb + SK + (uint32_t)(kb & 1) * 32768;
    const uint32_t vB = sb + SV + (uint32_t)(kb & 1) * 32768;
    const uint32_t mB = sb + SM2 + (uint32_t)(kb & 1) * MBUF;
#pragma unroll
    for (int i = 0; i < 4; i++) {
      int idx = tid + i * 512;
      int r = idx >> 4, ch = idx & 15;
      uint32_t sw = (uint32_t)r * 256 + (uint32_t)((ch ^ (r & 7)) << 4);
      cp16(kB + sw, g_kh + (size_t)(kcol + r) * DH + ch * 8);
      cp16(vB + sw, g_vh + (size_t)(kcol + r) * DH + ch * 8);
    }
#pragma unroll
    for (int i = 0; i < 4; i++) {
      int idx = tid + i * 512;     // 128 rows x 16 chunks of 8B
      int r = idx >> 4, ch = idx & 15;
      cp8(mB + (uint32_t)r * MSTRIDE + (uint32_t)(ch << 3),
          mp + (size_t)(qbase + r) * NTOK + kcol + ch * 8);
    }
    CP_COMMIT();
  };

  issue(0);

  // stage Q into resident smem (re-ldmatrix'd every iteration)
#pragma unroll
  for (int i = 0; i < 4; i++) {
    int idx = tid + i * 512;
    int r = idx >> 4, ch = idx & 15;
    uint4 v = *(const uint4*)(g_qh + (size_t)(qbase + r) * DH + ch * 8);
    *(uint4*)(smem + SQ + r * 256 + ((ch ^ (r & 7)) << 4)) = v;
  }

  float o[2][4][4];
#pragma unroll
  for (int m = 0; m < 2; m++)
#pragma unroll
    for (int nt = 0; nt < 4; nt++)
#pragma unroll
      for (int r = 0; r < 4; r++) o[m][nt][r] = 0.f;
  float lp[2][2] = {{0.f, 0.f}, {0.f, 0.f}};

  for (int kb = 0; kb < 32; kb++) {
    CP_WAIT0();
    __syncthreads();
    if (kb < 31) issue(kb + 1);

    const uint32_t bufK = sb + SK + (uint32_t)(kb & 1) * 32768;
    const uint32_t bufV = sb + SV + (uint32_t)(kb & 1) * 32768;
    const uint32_t kB = bufK + (uint32_t)(wc * 32 + x7) * 256;
    const uint32_t mBb = sb + SM2 + (uint32_t)(kb & 1) * MBUF + (uint32_t)(wc * 32 + c4 * 2);

    // ---- per 16-row half: S = Q@K^T, softmax, stmatrix P ----
#pragma unroll
    for (int mt = 0; mt < 2; mt++) {
      uint32_t qa[8][4];
      const uint32_t qB = sb + SQ + (uint32_t)(wr * 32 + mt * 16 + l15) * 256;
#pragma unroll
      for (int ks = 0; ks < 8; ks++)
        ldm_x4(qa[ks], qB + (((ks * 2 + hiA) ^ x7) << 4));

      float s[4][4];
#pragma unroll
      for (int nt = 0; nt < 4; nt++)
#pragma unroll
        for (int r = 0; r < 4; r++) s[nt][r] = 0.f;
#pragma unroll
      for (int ks = 0; ks < 8; ks++) {
#pragma unroll
        for (int j = 0; j < 2; j++) {
          uint32_t b[4];
          ldm_x4(b, kB + (uint32_t)(j * 2 + q2) * 8 * 256 + (((ks * 2 + hiB) ^ x7) << 4));
          mma16816(s[2 * j], qa[ks], b);
          mma16816(s[2 * j + 1], qa[ks], b + 2);
        }
      }

      uint32_t pk[2][4];
#pragma unroll
      for (int h = 0; h < 2; h++) {
        int rowl = wr * 32 + mt * 16 + h * 8 + g;
        uint32_t mrow = mBb + (uint32_t)rowl * MSTRIDE;
        unsigned short mv[4];
#pragma unroll
        for (int nt = 0; nt < 4; nt++)
          asm volatile("ld.shared.u16 %0, [%1];" : "=h"(mv[nt]) : "r"(mrow + nt * 8));
        __half2 hs = __halves2half2(__float2half(0.f), __float2half(0.f));
#pragma unroll
        for (int nt = 0; nt < 4; nt++) {
          uint32_t m2u = 0x3C003C00u -
              (((mv[nt] & 1u) | (((uint32_t)mv[nt] & 0x100u) << 8)) * 0x3C00u);
          __half2 m2 = *(__half2*)&m2u;
          __half2 sh = __floats2half2_rn(s[nt][h * 2], s[nt][h * 2 + 1]);
          __half2 p = __hmul2(hexp2_(sh), m2);
          pk[h][nt] = *(uint32_t*)&p;
          hs = __hadd2(hs, p);
        }
        float2 f = __half22float2(hs);
        lp[mt][h] += f.x + f.y;
      }
      // before the first P overwrite: prior PV reads by this wr-group must be done
      if (mt == 0) asm volatile("bar.sync %0, 128;" :: "r"(barid) : "memory");
      int srow = wr * 32 + mt * 16 + hh * 8 + r8;
      uint32_t sbase = sb + SP + (uint32_t)srow * 256;
      int sr7 = srow & 7;
#pragma unroll
      for (int j = 0; j < 2; j++) {
        uint32_t addr = sbase + (uint32_t)(((wc * 4 + 2 * j + ntp) ^ sr7) << 4);
        stm_x4(addr, pk[0][2 * j], pk[1][2 * j], pk[0][2 * j + 1], pk[1][2 * j + 1]);
      }
    }
    asm volatile("bar.sync %0, 128;" :: "r"(barid) : "memory");

    // ---- O += P @ V ----
    const uint32_t pB = sb + SP + (uint32_t)(wr * 32 + l15) * 256;
#pragma unroll
    for (int ks = 0; ks < 8; ks++) {
      uint32_t a0[4], a1[4];
      ldm_x4(a0, pB + (((ks * 2 + hiA) ^ x7) << 4));
      ldm_x4(a1, pB + 16 * 256 + (((ks * 2 + hiA) ^ x7) << 4));
      uint32_t vrow = bufV + (uint32_t)(ks * 16 + l15) * 256;
#pragma unroll
      for (int j = 0; j < 2; j++) {
        uint32_t b[4];
        ldm_x4t(b, vrow + (uint32_t)(((wc * 4 + j * 2 + q2) ^ x7) << 4));
        mma16816(o[0][2 * j], a0, b);
        mma16816(o[1][2 * j], a1, b);
        mma16816(o[0][2 * j + 1], a0, b + 2);
        mma16816(o[1][2 * j + 1], a1, b + 2);
      }
    }
  }

  // ---- l reduction across c4 lanes and the 4 wc groups ----
  __syncthreads();                       // all PV reads of P done -> reuse P region
  float* smL = (float*)(smem + SP);      // [4 wc][128 rows]
#pragma unroll
  for (int mt = 0; mt < 2; mt++)
#pragma unroll
    for (int h = 0; h < 2; h++) {
      float v = lp[mt][h];
      v += __shfl_xor_sync(0xffffffffu, v, 1);
      v += __shfl_xor_sync(0xffffffffu, v, 2);
      lp[mt][h] = v;
    }
  if (c4 == 0) {
#pragma unroll
    for (int mt = 0; mt < 2; mt++)
#pragma unroll
      for (int h = 0; h < 2; h++)
        smL[wc * 128 + wr * 32 + mt * 16 + h * 8 + g] = lp[mt][h];
  }
  __syncthreads();

#pragma unroll
  for (int mt = 0; mt < 2; mt++)
#pragma unroll
    for (int h = 0; h < 2; h++) {
      int rowl = wr * 32 + mt * 16 + h * 8 + g;
      float lt = smL[rowl] + smL[128 + rowl] + smL[256 + rowl] + smL[384 + rowl];
      if (wc == 0 && c4 == 0) g_l[split][qbase + rowl] = lt;
#pragma unroll
      for (int nt = 0; nt < 4; nt++) {
        int col = wc * 32 + nt * 8 + c4 * 2;
        float2 ov = make_float2(o[mt][nt][h * 2], o[mt][nt][h * 2 + 1]);
        *(float2*)(&g_O[split][(size_t)(qbase + rowl) * DH + col]) = ov;
      }
    }
}

// ---------------- combine splits ----------------
__global__ __launch_bounds__(256) void combine_kernel(float* __restrict__ out) {
  int i = blockIdx.x * 256 + threadIdx.x;
  int row = i >> 7;
  float l = g_l[0][row] + g_l[1][row];
  out[i] = (g_O[0][i] + g_O[1][i]) / l;
}

// ---------------- launch ----------------
extern "C" void kernel_launch(void* const* d_in, const int* in_sizes, int n_in,
                              void* d_out, int out_size) {
  const float* x0 = nullptr;
  const void*  mask = nullptr;
  const float* wqkv = nullptr;
  for (int i = 0; i < n_in; i++) {
    long sz = in_sizes[i];
    if (sz == (long)NTOK * HCH)        x0   = (const float*)d_in[i];
    else if (sz == (long)NTOK * NTOK)  mask = d_in[i];
    else if (sz == (long)3 * DH * HCH) wqkv = (const float*)d_in[i];
  }

  // 1: mask detect+compact
  mask_cvt_kernel<<<(int)((size_t)NTOK * NTOK / 16 / 256), 256>>>(
      (const unsigned*)mask, (const uint8_t*)mask);

  // 2: fp32->fp16 (x and W)
  cvt_kernel<<<(NX4 + NW4) / 256, 256>>>(x0, wqkv);

  // 3: QKV GEMM (2 CTAs/SM)
  cudaFuncSetAttribute(qkv_kernel, cudaFuncAttributeMaxDynamicSharedMemorySize, 49152);
  dim3 ggrid(NTOK / 64, 3);
  qkv_kernel<<<ggrid, 256, 49152>>>();

  // 4: attention (512 threads)
  cudaFuncSetAttribute(attn_kernel, cudaFuncAttributeMaxDynamicSharedMemorySize, A_SMEM);
  attn_kernel<<<NTOK / 128 * 2, 512, A_SMEM>>>();

  // 5: combine
  combine_kernel<<<NTOK * DH / 256, 256>>>((float*)d_out);
}

// round 11
// speedup vs baseline: 1.1807x; 1.1807x over previous
#include <cuda_runtime.h>
#include <cuda_fp16.h>
#include <cstdint>

#define NTOK 8192
#define HCH  2048
#define DH   128

// ---------------- device scratch ----------------
__device__ __align__(16) __half g_xh[NTOK * HCH];
__device__ __align__(16) __half g_wh[384 * HCH];
__device__ __align__(16) __half g_qh[NTOK * DH];   // scale folded
__device__ __align__(16) __half g_kh[NTOK * DH];
__device__ __align__(16) __half g_vh[NTOK * DH];
__device__ __align__(16) float  g_O[2][NTOK * DH]; // unnormalized per split
__device__ float g_l[2][NTOK];
__device__ uint8_t g_mask8[(size_t)NTOK * NTOK];
__device__ const uint8_t* g_mptr;

// ---------------- helpers ----------------
__device__ __forceinline__ uint32_t smem_u32(const void* p) {
  uint32_t a;
  asm("{ .reg .u64 t; cvta.to.shared.u64 t, %1; cvt.u32.u64 %0, t; }" : "=r"(a) : "l"(p));
  return a;
}
__device__ __forceinline__ void ldm_x4(uint32_t* r, uint32_t a) {
  asm volatile("ldmatrix.sync.aligned.m8n8.x4.shared.b16 {%0,%1,%2,%3}, [%4];"
    : "=r"(r[0]), "=r"(r[1]), "=r"(r[2]), "=r"(r[3]) : "r"(a));
}
__device__ __forceinline__ void ldm_x4t(uint32_t* r, uint32_t a) {
  asm volatile("ldmatrix.sync.aligned.m8n8.x4.trans.shared.b16 {%0,%1,%2,%3}, [%4];"
    : "=r"(r[0]), "=r"(r[1]), "=r"(r[2]), "=r"(r[3]) : "r"(a));
}
__device__ __forceinline__ void stm_x4(uint32_t a, uint32_t r0, uint32_t r1,
                                       uint32_t r2, uint32_t r3) {
  asm volatile("stmatrix.sync.aligned.m8n8.x4.shared.b16 [%0], {%1,%2,%3,%4};"
    :: "r"(a), "r"(r0), "r"(r1), "r"(r2), "r"(r3) : "memory");
}
__device__ __forceinline__ void mma16816(float* d, const uint32_t* a, const uint32_t* b) {
  asm volatile("mma.sync.aligned.m16n8k16.row.col.f32.f16.f16.f32 "
    "{%0,%1,%2,%3}, {%4,%5,%6,%7}, {%8,%9}, {%0,%1,%2,%3};"
    : "+f"(d[0]), "+f"(d[1]), "+f"(d[2]), "+f"(d[3])
    : "r"(a[0]), "r"(a[1]), "r"(a[2]), "r"(a[3]), "r"(b[0]), "r"(b[1]));
}
__device__ __forceinline__ void cp16(uint32_t dst, const void* src) {
  asm volatile("cp.async.cg.shared.global [%0], [%1], 16;" :: "r"(dst), "l"(src) : "memory");
}
#define CP_COMMIT() asm volatile("cp.async.commit_group;" ::: "memory")
#define CP_WAIT0()  asm volatile("cp.async.wait_group 0;" ::: "memory")
#define CP_WAIT1()  asm volatile("cp.async.wait_group 1;" ::: "memory")
__device__ __forceinline__ __half2 hexp2_(__half2 x) {
  uint32_t r, a = *(uint32_t*)&x;
  asm("ex2.approx.f16x2 %0, %1;" : "=r"(r) : "r"(a));
  return *(__half2*)&r;
}
__device__ __forceinline__ uint32_t pack_h2(float x, float y) {
  __half2 h = __floats2half2_rn(x, y);
  return *(uint32_t*)&h;
}

// ---------------- mask detect + compact (fused, parallel detect) ----------------
__global__ __launch_bounds__(256) void mask_cvt_kernel(const unsigned* __restrict__ m,
                                                       const uint8_t* __restrict__ morig) {
  __shared__ int s_ok;
  if (threadIdx.x == 0) s_ok = 1;
  __syncthreads();
  if (threadIdx.x < 64) {
    unsigned w = m[threadIdx.x];
    if (w > 1u && w != 0x3f800000u) s_ok = 0;   // benign race: all writers store 0
  }
  __syncthreads();
  if (threadIdx.x == 0 && blockIdx.x == 0)
    g_mptr = s_ok ? (const uint8_t*)g_mask8 : morig;
  if (!s_ok) return;
  size_t i = (size_t)blockIdx.x * 256 + threadIdx.x;   // 16 outputs each
  const uint4* src = (const uint4*)m + i * 4;
  uint4 a = src[0], b = src[1], c = src[2], d = src[3];
  uint4 o;
  o.x = (a.x?1u:0u)|((a.y?1u:0u)<<8)|((a.z?1u:0u)<<16)|((a.w?1u:0u)<<24);
  o.y = (b.x?1u:0u)|((b.y?1u:0u)<<8)|((b.z?1u:0u)<<16)|((b.w?1u:0u)<<24);
  o.z = (c.x?1u:0u)|((c.y?1u:0u)<<8)|((c.z?1u:0u)<<16)|((c.w?1u:0u)<<24);
  o.w = (d.x?1u:0u)|((d.y?1u:0u)<<8)|((d.z?1u:0u)<<16)|((d.w?1u:0u)<<24);
  *(uint4*)(g_mask8 + i * 16) = o;
}

// ---------------- fp32 -> fp16 (x and W fused) ----------------
#define NX4 (NTOK * HCH / 4)
#define NW4 (384 * HCH / 4)
__global__ __launch_bounds__(256) void cvt_kernel(const float* __restrict__ x,
                                                  const float* __restrict__ w) {
  int i = blockIdx.x * 256 + threadIdx.x;
  const float* src;
  __half* dst;
  int j;
  if (i < NX4) { src = x; dst = g_xh; j = i; }
  else         { src = w; dst = g_wh; j = i - NX4; }
  float4 v = ((const float4*)src)[j];
  uint2 o; o.x = pack_h2(v.x, v.y); o.y = pack_h2(v.z, v.w);
  ((uint2*)dst)[j] = o;
}

// ---------------- QKV GEMM (mma.sync fp16, 3-stage cp.async pipeline) ----------------
// BM=64, BN=128, BK=64; grid (128, 3). smem: A 3x8KB at 0, B 3x16KB at 24K = 72KB.
__global__ __launch_bounds__(256) void qkv_kernel() {
  extern __shared__ __align__(16) char smem[];
  const uint32_t sb = smem_u32(smem);
  const int tid = threadIdx.x, lane = tid & 31, wid = tid >> 5;
  const int wr = wid & 3, wc = wid >> 2;
  const int g = lane >> 2, c4 = lane & 3;
  const int m0 = blockIdx.x * 64;
  const int which = blockIdx.y;
  const __half* wsrc = g_wh + (size_t)which * 128 * HCH;

  float acc[8][4];
#pragma unroll
  for (int nt = 0; nt < 8; nt++)
#pragma unroll
    for (int r = 0; r < 4; r++) acc[nt][r] = 0.f;

  const int x7 = lane & 7, hiA = lane >> 4, hiB = (lane >> 3) & 1, q2 = (lane >> 4) & 1;
  const int l15 = lane & 15;

  auto issue = [&](int kc) {
    int st = kc % 3;
    uint32_t bufA = sb + (uint32_t)st * 8192;
    uint32_t bufB = sb + 24576 + (uint32_t)st * 16384;
#pragma unroll
    for (int i = 0; i < 2; i++) {
      int idx = tid + i * 256;
      int r = idx >> 3, ch = idx & 7;
      uint32_t sw = (uint32_t)r * 128 + (uint32_t)((ch ^ (r & 7)) << 4);
      cp16(bufA + sw, g_xh + (size_t)(m0 + r) * HCH + kc * 64 + ch * 8);
    }
#pragma unroll
    for (int i = 0; i < 4; i++) {
      int idx = tid + i * 256;
      int r = idx >> 3, ch = idx & 7;
      uint32_t sw = (uint32_t)r * 128 + (uint32_t)((ch ^ (r & 7)) << 4);
      cp16(bufB + sw, wsrc + (size_t)r * HCH + kc * 64 + ch * 8);
    }
    CP_COMMIT();
  };

  issue(0);
  issue(1);
  for (int kc = 0; kc < 32; kc++) {
    if (kc < 31) { CP_WAIT1(); } else { CP_WAIT0(); }
    __syncthreads();
    if (kc < 30) issue(kc + 2);
    int st = kc % 3;
    const uint32_t bufA = sb + (uint32_t)st * 8192;
    const uint32_t bufB = sb + 24576 + (uint32_t)st * 16384;
    const uint32_t aBase = bufA + (uint32_t)(wr * 16 + l15) * 128;
    const uint32_t bBase = bufB + (uint32_t)(wc * 64 + x7) * 128;
#pragma unroll
    for (int ks = 0; ks < 4; ks++) {
      uint32_t a0[4];
      ldm_x4(a0, aBase + (((ks * 2 + hiA) ^ x7) << 4));
#pragma unroll
      for (int nt = 0; nt < 8; nt += 2) {
        uint32_t b[4];
        ldm_x4(b, bBase + (uint32_t)(nt + q2) * 8 * 128 + (((ks * 2 + hiB) ^ x7) << 4));
        mma16816(acc[nt], a0, b);
        mma16816(acc[nt + 1], a0, b + 2);
      }
    }
  }

  const float sc = (which == 0) ? (1.4426950408889634f / 128.0f) : 1.0f;
  __half* dst = (which == 0) ? g_qh : (which == 1) ? g_kh : g_vh;
#pragma unroll
  for (int h = 0; h < 2; h++) {
    int row = m0 + wr * 16 + g + h * 8;
#pragma unroll
    for (int nt = 0; nt < 8; nt++) {
      int col = wc * 64 + nt * 8 + c4 * 2;
      *(uint32_t*)(dst + (size_t)row * DH + col) =
          pack_h2(acc[nt][h * 2] * sc, acc[nt][h * 2 + 1] * sc);
    }
  }
}

// ---------------- attention (R8 verbatim — best measured: 109.4us) ----------------
// grid 128 = 64 q-tiles x 2 kv-splits. BM=BN=128, 8 warps (4x2).
// smem: K 2x32KB, V 2x32KB, P 32KB, mask 2x18KB(stride 144), L 1KB
#define SK 0
#define SV 65536
#define SP 131072
#define SM2 163840
#define MSTRIDE 144
#define MBUF (128 * MSTRIDE)
#define SL (SM2 + 2 * MBUF)
#define A_SMEM (SL + 1024)

__global__ __launch_bounds__(256, 1) void attn_kernel() {
  extern __shared__ __align__(16) char smem[];
  const uint32_t sb = smem_u32(smem);
  const int tid = threadIdx.x, lane = tid & 31, wid = tid >> 5;
  const int wr = wid & 3, wc = wid >> 2;
  const int g = lane >> 2, c4 = lane & 3;
  const int qt = blockIdx.x >> 1;
  const int qbase = qt * 128;
  const int split = blockIdx.x & 1;
  const uint8_t* mp = g_mptr;
  const int barid = wr + 1;

  const int x7 = lane & 7, hiA = lane >> 4, hiB = (lane >> 3) & 1, q2 = (lane >> 4) & 1;
  const int l15 = lane & 15;

  auto issue = [&](int kb) {
    const int kcol = split * 4096 + kb * 128;
    const uint32_t kB = sb + SK + (uint32_t)(kb & 1) * 32768;
    const uint32_t vB = sb + SV + (uint32_t)(kb & 1) * 32768;
    const uint32_t mB = sb + SM2 + (uint32_t)(kb & 1) * MBUF;
#pragma unroll
    for (int i = 0; i < 8; i++) {
      int idx = tid + i * 256;
      int r = idx >> 4, ch = idx & 15;
      uint32_t sw = (uint32_t)r * 256 + (uint32_t)((ch ^ (r & 7)) << 4);
      cp16(kB + sw, g_kh + (size_t)(kcol + r) * DH + ch * 8);
      cp16(vB + sw, g_vh + (size_t)(kcol + r) * DH + ch * 8);
    }
#pragma unroll
    for (int i = 0; i < 4; i++) {
      int idx = tid + i * 256;
      int r = idx >> 3, ch = idx & 7;
      cp16(mB + (uint32_t)r * MSTRIDE + (uint32_t)(ch << 4),
           mp + (size_t)(qbase + r) * NTOK + kcol + ch * 16);
    }
    CP_COMMIT();
  };

  issue(0);

  // stage Q into the P region, extract fragments into registers
#pragma unroll
  for (int i = 0; i < 8; i++) {
    int idx = tid + i * 256;
    int r = idx >> 4, ch = idx & 15;
    uint4 v = *(const uint4*)(g_qh + (size_t)(qbase + r) * DH + ch * 8);
    *(uint4*)(smem + SP + r * 256 + ((ch ^ (r & 7)) << 4)) = v;
  }
  __syncthreads();
  uint32_t qa[8][2][4];
  {
    const uint32_t qB = sb + SP + (uint32_t)(wr * 32 + l15) * 256;
#pragma unroll
    for (int ks = 0; ks < 8; ks++) {
      ldm_x4(qa[ks][0], qB + (((ks * 2 + hiA) ^ x7) << 4));
      ldm_x4(qa[ks][1], qB + 16 * 256 + (((ks * 2 + hiA) ^ x7) << 4));
    }
  }
  __syncthreads();   // everyone has Q frags before P overwrites begin

  float o[2][8][4];
#pragma unroll
  for (int mt = 0; mt < 2; mt++)
#pragma unroll
    for (int nt = 0; nt < 8; nt++)
#pragma unroll
      for (int r = 0; r < 4; r++) o[mt][nt][r] = 0.f;
  float lp[2][2] = {{0.f, 0.f}, {0.f, 0.f}};

  const int t8 = lane >> 3;            // stmatrix tile index
  const int hh = t8 & 1, ntp = t8 >> 1, r8 = lane & 7;

  for (int kb = 0; kb < 32; kb++) {
    CP_WAIT0();
    __syncthreads();
    if (kb < 31) issue(kb + 1);

    const uint32_t kB = sb + SK + (uint32_t)(kb & 1) * 32768 + (uint32_t)(wc * 64 + x7) * 256;
    const uint32_t vB = sb + SV + (uint32_t)(kb & 1) * 32768 + (uint32_t)l15 * 256;
    const uint32_t mB = sb + SM2 + (uint32_t)(kb & 1) * MBUF + (uint32_t)(wc * 64 + c4 * 2);

    // ---- S = Q @ K^T ----
    float s[2][8][4];
#pragma unroll
    for (int mt = 0; mt < 2; mt++)
#pragma unroll
      for (int nt = 0; nt < 8; nt++)
#pragma unroll
        for (int r = 0; r < 4; r++) s[mt][nt][r] = 0.f;
#pragma unroll
    for (int ks = 0; ks < 8; ks++) {
#pragma unroll
      for (int nt = 0; nt < 8; nt += 2) {
        uint32_t b[4];
        ldm_x4(b, kB + (uint32_t)(nt + q2) * 8 * 256 + (((ks * 2 + hiB) ^ x7) << 4));
        mma16816(s[0][nt], qa[ks][0], b);
        mma16816(s[1][nt], qa[ks][1], b);
        mma16816(s[0][nt + 1], qa[ks][0], b + 2);
        mma16816(s[1][nt + 1], qa[ks][1], b + 2);
      }
    }

    // ---- fp16x2 softmax (multiplier from mask u16), stmatrix P ----
    asm volatile("bar.sync %0, 64;" :: "r"(barid) : "memory");
#pragma unroll
    for (int mt = 0; mt < 2; mt++) {
      uint32_t pk[2][8];
#pragma unroll
      for (int h = 0; h < 2; h++) {
        int rowl = wr * 32 + mt * 16 + h * 8 + g;
        uint32_t mrow = mB + (uint32_t)rowl * MSTRIDE;
        unsigned short mv[8];
#pragma unroll
        for (int nt = 0; nt < 8; nt++)
          asm volatile("ld.shared.u16 %0, [%1];" : "=h"(mv[nt]) : "r"(mrow + nt * 8));
        __half2 hs = __halves2half2(__float2half(0.f), __float2half(0.f));
#pragma unroll
        for (int nt = 0; nt < 8; nt++) {
          uint32_t m2u = 0x3C003C00u -
              (((mv[nt] & 1u) | (((uint32_t)mv[nt] & 0x100u) << 8)) * 0x3C00u);
          __half2 m2 = *(__half2*)&m2u;
          __half2 sh = __floats2half2_rn(s[mt][nt][h * 2], s[mt][nt][h * 2 + 1]);
          __half2 p = __hmul2(hexp2_(sh), m2);
          pk[h][nt] = *(uint32_t*)&p;
          hs = __hadd2(hs, p);
        }
        float2 f = __half22float2(hs);
        lp[mt][h] += f.x + f.y;
      }
      int srow = wr * 32 + mt * 16 + hh * 8 + r8;
      uint32_t sbase = sb + SP + (uint32_t)srow * 256;
      int sr7 = srow & 7;
#pragma unroll
      for (int j = 0; j < 4; j++) {
        int ntj = 2 * j + ntp;
        uint32_t addr = sbase + (uint32_t)(((wc * 8 + ntj) ^ sr7) << 4);
        stm_x4(addr, pk[0][2 * j], pk[1][2 * j], pk[0][2 * j + 1], pk[1][2 * j + 1]);
      }
    }
    asm volatile("bar.sync %0, 64;" :: "r"(barid) : "memory");

    // ---- O += P @ V ----
    const uint32_t pB = sb + SP + (uint32_t)(wr * 32 + l15) * 256;
#pragma unroll
    for (int ks = 0; ks < 8; ks++) {
      uint32_t a0[4], a1[4];
      ldm_x4(a0, pB + (((ks * 2 + hiA) ^ x7) << 4));
      ldm_x4(a1, pB + 16 * 256 + (((ks * 2 + hiA) ^ x7) << 4));
      uint32_t vrow = vB + (uint32_t)(ks * 16) * 256;
#pragma unroll
      for (int nt = 0; nt < 8; nt += 2) {
        uint32_t b[4];
        ldm_x4t(b, vrow + (uint32_t)(((wc * 8 + nt + q2) ^ x7) << 4));
        mma16816(o[0][nt], a0, b);
        mma16816(o[1][nt], a1, b);
        mma16816(o[0][nt + 1], a0, b + 2);
        mma16816(o[1][nt + 1], a1, b + 2);
      }
    }
  }

  // ---- l reduction ----
  float* smL = (float*)(smem + SL);   // [2][128]
#pragma unroll
  for (int mt = 0; mt < 2; mt++)
#pragma unroll
    for (int h = 0; h < 2; h++) {
      float v = lp[mt][h];
      v += __shfl_xor_sync(0xffffffffu, v, 1);
      v += __shfl_xor_sync(0xffffffffu, v, 2);
      lp[mt][h] = v;
    }
  __syncthreads();
  if (c4 == 0) {
#pragma unroll
    for (int mt = 0; mt < 2; mt++)
#pragma unroll
      for (int h = 0; h < 2; h++)
        smL[wc * 128 + wr * 32 + mt * 16 + g + h * 8] = lp[mt][h];
  }
  __syncthreads();

#pragma unroll
  for (int mt = 0; mt < 2; mt++)
#pragma unroll
    for (int h = 0; h < 2; h++) {
      int rowl = wr * 32 + mt * 16 + g + h * 8;
      float lt = smL[rowl] + smL[128 + rowl];
      if (wc == 0 && c4 == 0) g_l[split][qbase + rowl] = lt;
#pragma unroll
      for (int nt = 0; nt < 8; nt++) {
        int col = wc * 64 + nt * 8 + c4 * 2;
        float2 ov = make_float2(o[mt][nt][h * 2], o[mt][nt][h * 2 + 1]);
        *(float2*)(&g_O[split][(size_t)(qbase + rowl) * DH + col]) = ov;
      }
    }
}

// ---------------- combine splits ----------------
__global__ __launch_bounds__(256) void combine_kernel(float* __restrict__ out) {
  int i = blockIdx.x * 256 + threadIdx.x;
  int row = i >> 7;
  float l = g_l[0][row] + g_l[1][row];
  out[i] = (g_O[0][i] + g_O[1][i]) / l;
}

// ---------------- launch ----------------
extern "C" void kernel_launch(void* const* d_in, const int* in_sizes, int n_in,
                              void* d_out, int out_size) {
  const float* x0 = nullptr;
  const void*  mask = nullptr;
  const float* wqkv = nullptr;
  for (int i = 0; i < n_in; i++) {
    long sz = in_sizes[i];
    if (sz == (long)NTOK * HCH)        x0   = (const float*)d_in[i];
    else if (sz == (long)NTOK * NTOK)  mask = d_in[i];
    else if (sz == (long)3 * DH * HCH) wqkv = (const float*)d_in[i];
  }

  // 1: mask detect+compact
  mask_cvt_kernel<<<(int)((size_t)NTOK * NTOK / 16 / 256), 256>>>(
      (const unsigned*)mask, (const uint8_t*)mask);

  // 2: fp32->fp16 (x and W)
  cvt_kernel<<<(NX4 + NW4) / 256, 256>>>(x0, wqkv);

  // 3: QKV GEMM (3-stage pipeline, 72KB smem)
  cudaFuncSetAttribute(qkv_kernel, cudaFuncAttributeMaxDynamicSharedMemorySize, 73728);
  dim3 ggrid(NTOK / 64, 3);
  qkv_kernel<<<ggrid, 256, 73728>>>();

  // 4: attention
  cudaFuncSetAttribute(attn_kernel, cudaFuncAttributeMaxDynamicSharedMemorySize, A_SMEM);
  attn_kernel<<<NTOK / 128 * 2, 256, A_SMEM>>>();

  // 5: combine
  combine_kernel<<<NTOK * DH / 256, 256>>>((float*)d_out);
}